// round 1
// baseline (speedup 1.0000x reference)
#include <cuda_runtime.h>
#include <cstdint>

// Problem shape (fixed): x [T,B,C,H,W], T=4,B=16,C=512,H=W=32 -> N=1024
#define TT 4
#define BB 16
#define CC 512
#define NN 1024
#define HEADS 8
#define DD 64
#define VTH 1.0f

#define BCN  ((size_t)BB * CC * NN)          // 8,388,608
#define TBCN ((size_t)TT * BB * CC * NN)     // 33,554,432

// ---------------- scratch (static device globals; no runtime allocation) ----
__device__ float g_Y[3ull * TBCN];   // pre-LIF conv outputs q,k,v
__device__ float g_S[3ull * TBCN];   // spikes q,k,v
__device__ float g_att[TBCN];        // attention pre-LIF
__device__ float g_Sa[TBCN];         // attention spikes
__device__ float g_P[TBCN];          // proj conv output
__device__ float g_kv[(size_t)TT * BB * HEADS * DD * DD]; // 2M floats

// ---------------------------------------------------------------------------
// Fused conv1x1 GEMM: Y_w[o,n] = sum_c W_w[o,c] * X[c,n] + b_w[o]
// per (t,b): X is [C,N] slice. Tile 64x64, K-tile 16, 256 thr, 4x4 microtile.
// NW=3 shares the X tile across three weight matrices.
// ---------------------------------------------------------------------------
template <int NW>
__global__ __launch_bounds__(256)
void conv1x1_gemm(const float* __restrict__ Xall,
                  const float* __restrict__ W0, const float* __restrict__ W1,
                  const float* __restrict__ W2,
                  const float* __restrict__ b0, const float* __restrict__ b1,
                  const float* __restrict__ b2,
                  float* __restrict__ Y0, float* __restrict__ Y1,
                  float* __restrict__ Y2)
{
    constexpr int BM = 64, BN = 64, BK = 16;
    const int tb = blockIdx.z;
    const int n0 = blockIdx.x * BN;
    const int o0 = blockIdx.y * BM;
    const float* X = Xall + (size_t)tb * CC * NN;

    __shared__ __align__(16) float Xs[BK][BN];          // [k][n]
    __shared__ __align__(16) float Ws[NW][BK][BM + 4];  // [k][o], stride 68

    const int tid = threadIdx.x;
    const int tx = tid & 15;       // n microtile
    const int ty = tid >> 4;       // o microtile

    float acc[NW][4][4];
#pragma unroll
    for (int w = 0; w < NW; w++)
#pragma unroll
        for (int i = 0; i < 4; i++)
#pragma unroll
            for (int j = 0; j < 4; j++) acc[w][i][j] = 0.f;

    const int xr = tid >> 4;             // 0..15 (k row)
    const int xc = (tid & 15) * 4;       // 0..60 (n col)
    const int wo = tid >> 2;             // 0..63 (o row)
    const int wk = (tid & 3) * 4;        // 0..12 (k col)

    const float* Wp_[3] = {W0, W1, W2};

    for (int c0 = 0; c0 < CC; c0 += BK) {
        // load X tile (coalesced float4)
        float4 xv = *(const float4*)(X + (size_t)(c0 + xr) * NN + n0 + xc);
        *(float4*)(&Xs[xr][xc]) = xv;
        // load W tiles, transpose into [k][o]
#pragma unroll
        for (int w = 0; w < NW; w++) {
            float4 wv = *(const float4*)(Wp_[w] + (size_t)(o0 + wo) * CC + c0 + wk);
            Ws[w][wk + 0][wo] = wv.x;
            Ws[w][wk + 1][wo] = wv.y;
            Ws[w][wk + 2][wo] = wv.z;
            Ws[w][wk + 3][wo] = wv.w;
        }
        __syncthreads();
#pragma unroll
        for (int kk = 0; kk < BK; kk++) {
            float4 xf = *(const float4*)(&Xs[kk][tx * 4]);
            float xfa[4] = {xf.x, xf.y, xf.z, xf.w};
#pragma unroll
            for (int w = 0; w < NW; w++) {
                float4 wf = *(const float4*)(&Ws[w][kk][ty * 4]);
                float wfa[4] = {wf.x, wf.y, wf.z, wf.w};
#pragma unroll
                for (int i = 0; i < 4; i++)
#pragma unroll
                    for (int j = 0; j < 4; j++)
                        acc[w][i][j] += wfa[i] * xfa[j];
            }
        }
        __syncthreads();
    }

    const float* bp_[3] = {b0, b1, b2};
    float* Yp_[3] = {Y0, Y1, Y2};
#pragma unroll
    for (int w = 0; w < NW; w++) {
#pragma unroll
        for (int i = 0; i < 4; i++) {
            const int o = o0 + ty * 4 + i;
            const float bb = bp_[w][o];
            float4 r;
            r.x = acc[w][i][0] + bb;
            r.y = acc[w][i][1] + bb;
            r.z = acc[w][i][2] + bb;
            r.w = acc[w][i][3] + bb;
            *(float4*)(Yp_[w] + ((size_t)tb * CC + o) * NN + n0 + tx * 4) = r;
        }
    }
}

// ---------------------------------------------------------------------------
// LIF over T (elementwise). which: 0..2 -> g_Y->g_S ; 3 -> g_att->g_Sa
// v += (x - v)/2 ; spike v>=1 ; hard reset.
// ---------------------------------------------------------------------------
__global__ void lif_kernel(int base)
{
    const int which = base + blockIdx.y;
    const float* in;
    float* out;
    if (which < 3) {
        in = g_Y + (size_t)which * TBCN;
        out = g_S + (size_t)which * TBCN;
    } else {
        in = g_att;
        out = g_Sa;
    }
    const size_t i = (size_t)blockIdx.x * blockDim.x + threadIdx.x;
    if (i >= BCN) return;
    float v = 0.f;
#pragma unroll
    for (int t = 0; t < TT; t++) {
        float xx = in[(size_t)t * BCN + i];
        v = v + (xx - v) * 0.5f;
        float s = (v >= VTH) ? 1.f : 0.f;
        out[(size_t)t * BCN + i] = s;
        v = (s != 0.f) ? 0.f : v;
    }
}

// ---------------------------------------------------------------------------
// kv[tbh][d][e] = sum_n Sk[h*64+d, n] * Sv[h*64+e, n]     (exact: integer counts)
// one block per (t,b,h); 64x64 output, K = N = 1024 in chunks of 32.
// ---------------------------------------------------------------------------
__global__ __launch_bounds__(256)
void kv_kernel()
{
    const int tbh = blockIdx.x;          // 512
    const int tb = tbh >> 3;
    const int h = tbh & 7;
    const float* K_ = g_S + 1ull * TBCN + ((size_t)tb * CC + h * DD) * NN;
    const float* V_ = g_S + 2ull * TBCN + ((size_t)tb * CC + h * DD) * NN;

    __shared__ __align__(16) float KsT[32][DD + 4];  // [n][d]
    __shared__ __align__(16) float VsT[32][DD + 4];

    const int tid = threadIdx.x;
    const int tx = tid & 15, ty = tid >> 4;

    float acc[4][4] = {};

    for (int nb = 0; nb < NN; nb += 32) {
#pragma unroll
        for (int r = 0; r < 2; r++) {
            int fid = r * 256 + tid;
            int dd = fid >> 3;
            int ng = (fid & 7) * 4;
            float4 k4 = *(const float4*)(K_ + (size_t)dd * NN + nb + ng);
            KsT[ng + 0][dd] = k4.x; KsT[ng + 1][dd] = k4.y;
            KsT[ng + 2][dd] = k4.z; KsT[ng + 3][dd] = k4.w;
            float4 v4 = *(const float4*)(V_ + (size_t)dd * NN + nb + ng);
            VsT[ng + 0][dd] = v4.x; VsT[ng + 1][dd] = v4.y;
            VsT[ng + 2][dd] = v4.z; VsT[ng + 3][dd] = v4.w;
        }
        __syncthreads();
#pragma unroll
        for (int nn = 0; nn < 32; nn++) {
            float4 kf = *(const float4*)(&KsT[nn][ty * 4]);
            float4 vf = *(const float4*)(&VsT[nn][tx * 4]);
            float ka[4] = {kf.x, kf.y, kf.z, kf.w};
            float va[4] = {vf.x, vf.y, vf.z, vf.w};
#pragma unroll
            for (int i = 0; i < 4; i++)
#pragma unroll
                for (int j = 0; j < 4; j++)
                    acc[i][j] += ka[i] * va[j];
        }
        __syncthreads();
    }

    float* kvout = g_kv + (size_t)tbh * DD * DD;
#pragma unroll
    for (int i = 0; i < 4; i++) {
        float4 r = {acc[i][0], acc[i][1], acc[i][2], acc[i][3]};
        *(float4*)(kvout + (size_t)(ty * 4 + i) * DD + tx * 4) = r;
    }
}

// ---------------------------------------------------------------------------
// att[t,b, h*64+e, n] = 0.125 * sum_d Sq[h*64+d, n] * kv[d][e]   (exact)
// block = (n-tile of 64) x (t,b,h). 64x64 tile, K=64.
// ---------------------------------------------------------------------------
__global__ __launch_bounds__(256)
void attn_out_kernel()
{
    const int tbh = blockIdx.y;
    const int tb = tbh >> 3;
    const int h = tbh & 7;
    const int n0 = blockIdx.x * 64;
    const float* Q_ = g_S + ((size_t)tb * CC + h * DD) * NN;
    const float* kvp = g_kv + (size_t)tbh * DD * DD;

    __shared__ __align__(16) float kvs[DD][DD + 4];  // [d][e]
    __shared__ __align__(16) float Qs[16][64];       // [d][n]

    const int tid = threadIdx.x;
    const int tx = tid & 15, ty = tid >> 4;

    // load whole kv (4096 floats = 4 float4 per thread)
#pragma unroll
    for (int r = 0; r < 4; r++) {
        int fid = r * 256 + tid;
        int dd = fid >> 4;
        int eg = (fid & 15) * 4;
        float4 v = *(const float4*)(kvp + (size_t)dd * DD + eg);
        *(float4*)(&kvs[dd][eg]) = v;
    }
    __syncthreads();

    float acc[4][4] = {};  // [e][n]

    for (int d0 = 0; d0 < DD; d0 += 16) {
        int qr = tid >> 4;
        int qc = (tid & 15) * 4;
        float4 qv = *(const float4*)(Q_ + (size_t)(d0 + qr) * NN + n0 + qc);
        *(float4*)(&Qs[qr][qc]) = qv;
        __syncthreads();
#pragma unroll
        for (int kk = 0; kk < 16; kk++) {
            float4 qf = *(const float4*)(&Qs[kk][tx * 4]);
            float4 kf = *(const float4*)(&kvs[d0 + kk][ty * 4]);
            float qa[4] = {qf.x, qf.y, qf.z, qf.w};
            float ka[4] = {kf.x, kf.y, kf.z, kf.w};
#pragma unroll
            for (int i = 0; i < 4; i++)
#pragma unroll
                for (int j = 0; j < 4; j++)
                    acc[i][j] += ka[i] * qa[j];
        }
        __syncthreads();
    }

#pragma unroll
    for (int i = 0; i < 4; i++) {
        const int e = ty * 4 + i;
        float4 r;
        r.x = acc[i][0] * 0.125f;
        r.y = acc[i][1] * 0.125f;
        r.z = acc[i][2] * 0.125f;
        r.w = acc[i][3] * 0.125f;
        *(float4*)(g_att + ((size_t)tb * CC + h * DD + e) * NN + n0 + tx * 4) = r;
    }
}

// ---------------------------------------------------------------------------
// conn LIF: v += ((proj + x) - v)/2 ; spike; reset. writes final output.
// ---------------------------------------------------------------------------
__global__ void connlif_kernel(const float* __restrict__ x, float* __restrict__ out)
{
    const size_t i = (size_t)blockIdx.x * blockDim.x + threadIdx.x;
    if (i >= BCN) return;
    float v = 0.f;
#pragma unroll
    for (int t = 0; t < TT; t++) {
        float p = g_P[(size_t)t * BCN + i];
        float xx = x[(size_t)t * BCN + i];
        float chg = p + xx;
        v = v + (chg - v) * 0.5f;
        float s = (v >= VTH) ? 1.f : 0.f;
        out[(size_t)t * BCN + i] = s;
        v = (s != 0.f) ? 0.f : v;
    }
}

// ---------------------------------------------------------------------------
extern "C" void kernel_launch(void* const* d_in, const int* in_sizes, int n_in,
                              void* d_out, int out_size)
{
    const float* x  = (const float*)d_in[0];
    const float* Wq = (const float*)d_in[1];
    const float* bq = (const float*)d_in[2];
    const float* Wk = (const float*)d_in[3];
    const float* bk = (const float*)d_in[4];
    const float* Wv = (const float*)d_in[5];
    const float* bv = (const float*)d_in[6];
    const float* Wp = (const float*)d_in[7];
    const float* bp = (const float*)d_in[8];
    float* out = (float*)d_out;

    void *pY = nullptr, *pSa = nullptr, *pP = nullptr;
    cudaGetSymbolAddress(&pY, g_Y);
    cudaGetSymbolAddress(&pSa, g_Sa);
    cudaGetSymbolAddress(&pP, g_P);
    float* Yf = (float*)pY;

    const dim3 gemm_grid(NN / 64, CC / 64, TT * BB);  // (16, 8, 64)
    const int lif_blocks = (int)(BCN / 256);          // 32768

    // 1. fused QKV conv GEMM
    conv1x1_gemm<3><<<gemm_grid, 256>>>(x, Wq, Wk, Wv, bq, bk, bv,
                                        Yf, Yf + TBCN, Yf + 2ull * TBCN);
    // 2. LIF on q,k,v
    lif_kernel<<<dim3(lif_blocks, 3), 256>>>(0);
    // 3. kv = K^T V per head
    kv_kernel<<<TT * BB * HEADS, 256>>>();
    // 4. out = Q @ kv * SCALE
    attn_out_kernel<<<dim3(NN / 64, TT * BB * HEADS), 256>>>();
    // 5. LIF on attention output
    lif_kernel<<<dim3(lif_blocks, 1), 256>>>(3);
    // 6. proj conv GEMM
    conv1x1_gemm<1><<<gemm_grid, 256>>>((const float*)pSa, Wp, nullptr, nullptr,
                                        bp, nullptr, nullptr,
                                        (float*)pP, nullptr, nullptr);
    // 7. connecting LIF with identity shortcut -> final spikes
    connlif_kernel<<<lif_blocks, 256>>>(x, out);
}